// round 12
// baseline (speedup 1.0000x reference)
#include <cuda_runtime.h>
#include <cuda_fp16.h>
#include <cstdint>
#include <cstddef>

#define NN   100000
#define NE   500000
#define NR   6
#define HID  128
#define NG   1024
#define NBLK 98          // ceil(NN / 1024)
#define TM   128
#define GEMM_GRID ((NN + TM - 1) / TM)   // 782

// ---------------- scratch (static device globals; no allocation) ----------------
__device__ __align__(16) __half g_h6[(size_t)NR * NN * HID];  // per-relation h (fp16)
__device__ __align__(16) float g_act[(size_t)NN * HID];
__device__ __align__(16) float g_als6[(size_t)NR * NN * 4];
__device__ __align__(16) float g_ald6[(size_t)NR * NN * 4];
__device__ __align__(16) __half g_ah[(size_t)NN * HID];       // fp16 activations
__device__ __align__(16) __half g_bh1[NR * HID * 64];         // layer1 W fp16 [r][n][k]
__device__ __align__(16) __half g_bh2[NR * HID * HID];        // layer2 W fp16 [r][n][k]
__device__ int   g_deg[NR * NN];
__device__ int   g_cursor[NR * NN];
__device__ int   g_rowptr[NR * (NN + 1)];
__device__ int   g_csrc[(size_t)NR * NE];
__device__ int   g_bsum[NR * 128];
__device__ int   g_gstart[NG + 1];
__device__ float g_scores[NN];
__device__ __align__(16) float g_pooled[NG * HID];

__device__ __forceinline__ uint32_t smem_to_u32(const void* p) {
    uint32_t a;
    asm("{ .reg .u64 t; cvta.to.shared.u64 t, %1; cvt.u32.u64 %0, t; }" : "=r"(a) : "l"(p));
    return a;
}

#define LDSM4(d, addr) \
    asm volatile("ldmatrix.sync.aligned.m8n8.x4.shared.b16 {%0,%1,%2,%3}, [%4];" \
        : "=r"((d)[0]), "=r"((d)[1]), "=r"((d)[2]), "=r"((d)[3]) : "r"(addr))

#define MMAF16(c, a, b0, b1) \
    asm volatile("mma.sync.aligned.m16n8k16.row.col.f32.f16.f16.f32 " \
        "{%0,%1,%2,%3}, {%4,%5,%6,%7}, {%8,%9}, {%0,%1,%2,%3};" \
        : "+f"((c)[0]), "+f"((c)[1]), "+f"((c)[2]), "+f"((c)[3]) \
        : "r"((a)[0]), "r"((a)[1]), "r"((a)[2]), "r"((a)[3]), "r"(b0), "r"(b1))

// ---------------- CSR build ----------------
__global__ void k_zero_counters() {
    int i = blockIdx.x * blockDim.x + threadIdx.x;
    if (i < NR * NN) { g_deg[i] = 0; g_cursor[i] = 0; }
}
__global__ void k_hist(const int* __restrict__ ei) {
    int i = blockIdx.x * blockDim.x + threadIdx.x;
    if (i >= NR * NE) return;
    int r = i / NE, e = i - r * NE;
    int dst = ei[((size_t)r * 2 + 1) * NE + e];
    atomicAdd(&g_deg[r * NN + dst], 1);
}
__global__ void k_scanA() {
    __shared__ int sh[1024];
    int r = blockIdx.y, blk = blockIdx.x, t = threadIdx.x;
    int n = blk * 1024 + t;
    int v = (n < NN) ? g_deg[r * NN + n] : 0;
    sh[t] = v;
    __syncthreads();
    for (int off = 1; off < 1024; off <<= 1) {
        int add = (t >= off) ? sh[t - off] : 0;
        __syncthreads();
        sh[t] += add;
        __syncthreads();
    }
    if (n < NN) g_rowptr[r * (NN + 1) + n + 1] = sh[t];
    if (t == 1023) g_bsum[r * 128 + blk] = sh[t];
}
__global__ void k_scanB() {
    int r = threadIdx.x;
    if (r >= NR) return;
    int run = 0;
    for (int b = 0; b < NBLK; b++) {
        int v = g_bsum[r * 128 + b];
        g_bsum[r * 128 + b] = run;
        run += v;
    }
}
__global__ void k_scanC() {
    int r = blockIdx.y, blk = blockIdx.x, t = threadIdx.x;
    int n = blk * 1024 + t;
    if (n < NN) g_rowptr[r * (NN + 1) + n + 1] += g_bsum[r * 128 + blk];
    if (n == 0) g_rowptr[r * (NN + 1)] = 0;
}
__global__ void k_scatter(const int* __restrict__ ei) {
    int i = blockIdx.x * blockDim.x + threadIdx.x;
    if (i >= NR * NE) return;
    int r = i / NE, e = i - r * NE;
    int src = ei[((size_t)r * 2 + 0) * NE + e];
    int dst = ei[((size_t)r * 2 + 1) * NE + e];
    int pos = g_rowptr[r * (NN + 1) + dst] + atomicAdd(&g_cursor[r * NN + dst], 1);
    g_csrc[(size_t)r * NE + pos] = src;
}

// ---------------- fp16 convert precompute ----------------
template <int K>
__global__ void k_split_a(const float* __restrict__ A) {
    int i = blockIdx.x * blockDim.x + threadIdx.x;
    if (i >= NN * K) return;
    g_ah[i] = __float2half(A[i]);
}
template <int K>
__global__ void k_split_w(const float* __restrict__ W, __half* __restrict__ Bh) {
    int i = blockIdx.x * blockDim.x + threadIdx.x;   // over NR*HID*K, [r][n][k]
    if (i >= NR * HID * K) return;
    int k = i % K;
    int n = (i / K) % HID;
    int r = i / (K * HID);
    Bh[i] = __float2half(W[((size_t)r * K + k) * HID + n]);
}

// ---------------- mma.sync fp16 GEMM + fused logits ----------------
// blockIdx.y = relation. K chunked by 64. D[128,128] = A@W^T, fp32 accum, fp16 out.
template <int K>
__global__ __launch_bounds__(256, 2)
void k_wmma(const __half* __restrict__ BhAll,
            const float* __restrict__ asrcAll, const float* __restrict__ adstAll) {
    constexpr int CH = 64;                 // K-chunk width
    constexpr int NCH = K / CH;
    constexpr int STRIDE = CH * 2 + 16;    // 144 bytes per row
    constexpr int TS = 128 * STRIDE;       // 18432 per tile
    constexpr int SEGS = CH / 8;           // 8 16B segments per row
    extern __shared__ char smem[];
    __shared__ float s_as[128], s_ad[128];
    const int tid = threadIdx.x;
    const int wid = tid >> 5, lane = tid & 31;
    const int warprow = wid & 3, warpcol = wid >> 2;
    const int row0 = blockIdx.x * TM;
    const int r = blockIdx.y;
    const __half* Bh = BhAll + (size_t)r * HID * K;

    if (tid < 128) { s_as[tid] = asrcAll[r * HID + tid]; s_ad[tid] = adstAll[r * HID + tid]; }

    const uint32_t sb = smem_to_u32(smem);
    const uint32_t aAddr = sb + (uint32_t)((warprow * 32 + (lane & 15)) * STRIDE + (((lane >> 4) << 3) << 1));
    const uint32_t bAddr = sb + TS +
        (uint32_t)((warpcol * 64 + (lane & 7) + ((lane >> 4) << 3)) * STRIDE + ((lane & 8) << 1));

    float acc[2][8][4];
#pragma unroll
    for (int mt = 0; mt < 2; mt++)
#pragma unroll
        for (int nt = 0; nt < 8; nt++)
#pragma unroll
            for (int j = 0; j < 4; j++) acc[mt][nt][j] = 0.0f;

    for (int c = 0; c < NCH; c++) {
        for (int u = tid; u < 128 * SEGS; u += 256) {
            int row = u >> 3, seg = u & 7;
            uint4 va = make_uint4(0, 0, 0, 0);
            if (row0 + row < NN) {
                size_t g = (size_t)(row0 + row) * K + c * CH + seg * 8;
                va = *(const uint4*)(g_ah + g);
            }
            *(uint4*)(smem + 0 * TS + row * STRIDE + seg * 16) = va;
            size_t b = (size_t)row * K + c * CH + seg * 8;
            *(uint4*)(smem + 1 * TS + row * STRIDE + seg * 16) = *(const uint4*)(Bh + b);
        }
        __syncthreads();

#pragma unroll
        for (int k0 = 0; k0 < CH; k0 += 16) {
            uint32_t ah[2][4], bh[4][4];
#pragma unroll
            for (int mt = 0; mt < 2; mt++)
                LDSM4(ah[mt], aAddr + mt * 16 * STRIDE + k0 * 2);
#pragma unroll
            for (int j = 0; j < 4; j++)
                LDSM4(bh[j], bAddr + j * 16 * STRIDE + k0 * 2);
#pragma unroll
            for (int mt = 0; mt < 2; mt++)
#pragma unroll
                for (int nt = 0; nt < 8; nt++) {
                    int j = nt >> 1, s = (nt & 1) * 2;
                    MMAF16(acc[mt][nt], ah[mt], bh[j][s], bh[j][s + 1]);
                }
        }
        __syncthreads();
    }

    // epilogue: store h (fp16) + fused attention logits
    const int quad = lane >> 2, ql = lane & 3;
    __half* Hout = g_h6 + (size_t)r * NN * HID;
    float ps[8], pd[8];
#pragma unroll
    for (int i = 0; i < 8; i++) { ps[i] = 0.f; pd[i] = 0.f; }

#pragma unroll
    for (int mt = 0; mt < 2; mt++) {
#pragma unroll
        for (int nt = 0; nt < 8; nt++) {
            int nc = warpcol * 64 + nt * 8 + 2 * ql;
            int hl = nt >> 2;
            float c0 = acc[mt][nt][0], c1 = acc[mt][nt][1];
            float c2 = acc[mt][nt][2], c3 = acc[mt][nt][3];
            ps[mt * 4 + 0 + hl] += c0 * s_as[nc] + c1 * s_as[nc + 1];
            pd[mt * 4 + 0 + hl] += c0 * s_ad[nc] + c1 * s_ad[nc + 1];
            ps[mt * 4 + 2 + hl] += c2 * s_as[nc] + c3 * s_as[nc + 1];
            pd[mt * 4 + 2 + hl] += c2 * s_ad[nc] + c3 * s_ad[nc + 1];
            int r0g = row0 + warprow * 32 + mt * 16 + quad;
            if (r0g < NN)
                *(__half2*)(Hout + (size_t)r0g * HID + nc) =
                    __floats2half2_rn(c0, c1);
            if (r0g + 8 < NN)
                *(__half2*)(Hout + (size_t)(r0g + 8) * HID + nc) =
                    __floats2half2_rn(c2, c3);
        }
    }
#pragma unroll
    for (int i = 0; i < 8; i++) {
        ps[i] += __shfl_xor_sync(0xffffffffu, ps[i], 1);
        ps[i] += __shfl_xor_sync(0xffffffffu, ps[i], 2);
        pd[i] += __shfl_xor_sync(0xffffffffu, pd[i], 1);
        pd[i] += __shfl_xor_sync(0xffffffffu, pd[i], 2);
    }
    if (ql == 0) {
#pragma unroll
        for (int mt = 0; mt < 2; mt++)
#pragma unroll
            for (int sub = 0; sub < 2; sub++) {
                int rg = row0 + warprow * 32 + mt * 16 + sub * 8 + quad;
                if (rg < NN) {
                    size_t off = ((size_t)r * NN + rg) * 4 + warpcol * 2;
                    *(float2*)(g_als6 + off) =
                        make_float2(ps[mt * 4 + sub * 2 + 0], ps[mt * 4 + sub * 2 + 1]);
                    *(float2*)(g_ald6 + off) =
                        make_float2(pd[mt * 4 + sub * 2 + 0], pd[mt * 4 + sub * 2 + 1]);
                }
            }
    }
}

// ---------------- GAT aggregation + softsign + LN (block per node, warp per relation)
// 192 threads: warp w handles relation w. Single-pass softmax. Warp 0 reduces over
// relations + Sum bias, then softsign + LN, emits fp16 (layer1) / fp32 (layer2).
template <bool EMIT_F16>
__global__ __launch_bounds__(192) void k_agg_ln(const float* __restrict__ bias,
                                                const float* __restrict__ gam,
                                                const float* __restrict__ bet) {
    __shared__ float sm[NR][HID];
    const int gw = blockIdx.x;
    const int wid = threadIdx.x >> 5, lane = threadIdx.x & 31;
    const int r = wid;

    const int* rp = g_rowptr + r * (NN + 1);
    int e0 = rp[gw], e1 = rp[gw + 1];
    float a0 = 0.f, a1 = 0.f, a2 = 0.f, a3 = 0.f;
    float d0 = 0.f, d1 = 0.f, d2 = 0.f, d3 = 0.f;
    if (e0 != e1) {
        const int* csrc = g_csrc + (size_t)r * NE;
        const float* als = g_als6 + (size_t)r * NN * 4;
        const __half* H = g_h6 + (size_t)r * NN * HID;
        float4 ad = *(const float4*)(g_ald6 + ((size_t)r * NN + gw) * 4);
        for (int e = e0; e < e1; e++) {
            int s = csrc[e];
            float4 as = *(const float4*)(als + s * 4);
            float t0 = as.x + ad.x; t0 = t0 > 0.f ? t0 : 0.2f * t0;
            float t1 = as.y + ad.y; t1 = t1 > 0.f ? t1 : 0.2f * t1;
            float t2 = as.z + ad.z; t2 = t2 > 0.f ? t2 : 0.2f * t2;
            float t3 = as.w + ad.w; t3 = t3 > 0.f ? t3 : 0.2f * t3;
            float e0x = __expf(t0), e1x = __expf(t1);
            float e2x = __expf(t2), e3x = __expf(t3);
            d0 += e0x; d1 += e1x; d2 += e2x; d3 += e3x;
            const __half* hp = H + (size_t)s * HID + lane;
            a0 += e0x * __half2float(hp[0]);
            a1 += e1x * __half2float(hp[32]);
            a2 += e2x * __half2float(hp[64]);
            a3 += e3x * __half2float(hp[96]);
        }
    }
    sm[r][lane]      = a0 / (d0 + 1e-16f);
    sm[r][lane + 32] = a1 / (d1 + 1e-16f);
    sm[r][lane + 64] = a2 / (d2 + 1e-16f);
    sm[r][lane + 96] = a3 / (d3 + 1e-16f);
    __syncthreads();

    if (wid == 0) {
        float o0 = 0.f, o1 = 0.f, o2 = 0.f, o3 = 0.f;
#pragma unroll
        for (int rr = 0; rr < NR; rr++) {
            o0 += sm[rr][lane]      + bias[rr * HID + lane];
            o1 += sm[rr][lane + 32] + bias[rr * HID + 32 + lane];
            o2 += sm[rr][lane + 64] + bias[rr * HID + 64 + lane];
            o3 += sm[rr][lane + 96] + bias[rr * HID + 96 + lane];
        }
        // softsign
        float s0 = o0 / (1.0f + fabsf(o0));
        float s1 = o1 / (1.0f + fabsf(o1));
        float s2 = o2 / (1.0f + fabsf(o2));
        float s3 = o3 / (1.0f + fabsf(o3));
        // LayerNorm across warp (128 channels)
        float sum = s0 + s1 + s2 + s3;
        float sq  = s0 * s0 + s1 * s1 + s2 * s2 + s3 * s3;
#pragma unroll
        for (int off = 16; off; off >>= 1) {
            sum += __shfl_xor_sync(0xffffffffu, sum, off);
            sq  += __shfl_xor_sync(0xffffffffu, sq, off);
        }
        float mu = sum * (1.0f / HID);
        float var = sq * (1.0f / HID) - mu * mu;
        float rs = rsqrtf(var + 1e-5f);
        float r0 = (s0 - mu) * rs * gam[lane]      + bet[lane];
        float r1 = (s1 - mu) * rs * gam[32 + lane] + bet[32 + lane];
        float r2 = (s2 - mu) * rs * gam[64 + lane] + bet[64 + lane];
        float r3 = (s3 - mu) * rs * gam[96 + lane] + bet[96 + lane];
        if (EMIT_F16) {
            __half* ap = g_ah + (size_t)gw * HID + lane;
            ap[0]  = __float2half(r0);
            ap[32] = __float2half(r1);
            ap[64] = __float2half(r2);
            ap[96] = __float2half(r3);
        } else {
            float* ap = g_act + (size_t)gw * HID + lane;
            ap[0] = r0; ap[32] = r1; ap[64] = r2; ap[96] = r3;
        }
    }
}

// ---------------- pooling ----------------
__global__ void k_scores(const float* __restrict__ q) {
    int gw = (blockIdx.x * blockDim.x + threadIdx.x) >> 5;
    int lane = threadIdx.x & 31;
    if (gw >= NN) return;
    float4 h = *(const float4*)(g_act + (size_t)gw * HID + lane * 4);
    float4 qq = *(const float4*)(q + lane * 4);
    float s = h.x * qq.x + h.y * qq.y + h.z * qq.z + h.w * qq.w;
#pragma unroll
    for (int off = 16; off; off >>= 1) s += __shfl_xor_sync(0xffffffffu, s, off);
    if (lane == 0) g_scores[gw] = s;
}

__global__ void k_gstart(const int* __restrict__ batch) {
    int n = blockIdx.x * blockDim.x + threadIdx.x;
    if (n >= NN) return;
    int b = batch[n];
    if (n == 0) {
        for (int g = 0; g <= b; g++) g_gstart[g] = 0;
    } else {
        int pb = batch[n - 1];
        for (int g = pb + 1; g <= b; g++) g_gstart[g] = n;
    }
    if (n == NN - 1) {
        for (int g = b + 1; g <= NG; g++) g_gstart[g] = NN;
    }
}

__global__ __launch_bounds__(128) void k_pool() {
    int g = blockIdx.x, t = threadIdx.x;
    int s = g_gstart[g], e = g_gstart[g + 1];
    __shared__ float red[128];
    __shared__ float sex[128];
    float m = -3.4e38f;
    for (int n = s + t; n < e; n += 128) m = fmaxf(m, g_scores[n]);
    red[t] = m;
    __syncthreads();
    for (int off = 64; off; off >>= 1) {
        if (t < off) red[t] = fmaxf(red[t], red[t + off]);
        __syncthreads();
    }
    m = red[0];
    __syncthreads();
    float acc = 0.f, den = 0.f;
    for (int base = s; base < e; base += 128) {
        int idx = base + t;
        float ex = (idx < e) ? __expf(g_scores[idx] - m) : 0.0f;
        den += ex;
        sex[t] = ex;
        __syncthreads();
        int lim = e - base; if (lim > 128) lim = 128;
        for (int j = 0; j < lim; j++)
            acc += sex[j] * g_act[(size_t)(base + j) * HID + t];
        __syncthreads();
    }
    red[t] = den;
    __syncthreads();
    for (int off = 64; off; off >>= 1) {
        if (t < off) red[t] += red[t + off];
        __syncthreads();
    }
    g_pooled[g * HID + t] = acc / (red[0] + 1e-16f);
}

__global__ __launch_bounds__(128) void k_proj(const float* __restrict__ Wp,
                                              const float* __restrict__ bp,
                                              float* __restrict__ out) {
    int g = blockIdx.x, t = threadIdx.x;
    float acc = bp[t];
    const float* p = g_pooled + g * HID;
#pragma unroll 8
    for (int k = 0; k < HID; k++) acc += p[k] * Wp[k * HID + t];
    out[g * HID + t] = acc;
}

// ---------------- orchestration ----------------
extern "C" void kernel_launch(void* const* d_in, const int* in_sizes, int n_in,
                              void* d_out, int out_size) {
    const float* x    = (const float*)d_in[0];
    const int*   ei   = (const int*)d_in[1];
    const int*   batch= (const int*)d_in[2];
    const float* W1  = (const float*)d_in[3];
    const float* as1 = (const float*)d_in[4];
    const float* ad1 = (const float*)d_in[5];
    const float* b1  = (const float*)d_in[6];
    const float* W2  = (const float*)d_in[7];
    const float* as2 = (const float*)d_in[8];
    const float* ad2 = (const float*)d_in[9];
    const float* b2  = (const float*)d_in[10];
    const float* g1  = (const float*)d_in[11];
    const float* be1 = (const float*)d_in[12];
    const float* g2  = (const float*)d_in[13];
    const float* be2 = (const float*)d_in[14];
    const float* q   = (const float*)d_in[15];
    const float* Wp  = (const float*)d_in[16];
    const float* bp  = (const float*)d_in[17];
    float* out = (float*)d_out;

    const int SMEM = 2 * 128 * (64 * 2 + 16);    // 36864 (A tile + B tile)
    cudaFuncSetAttribute(k_wmma<64>,  cudaFuncAttributeMaxDynamicSharedMemorySize, SMEM);
    cudaFuncSetAttribute(k_wmma<128>, cudaFuncAttributeMaxDynamicSharedMemorySize, SMEM);

    const int warpgrid = (NN * 32 + 255) / 256;
    const dim3 ggrid(GEMM_GRID, NR);

    // ncu profiles launch #4 -> layer-1 GEMM there
    k_split_a<64><<<(NN * 64 + 255) / 256, 256>>>(x);                          // 1
    k_split_w<64><<<(NR * HID * 64 + 255) / 256, 256>>>(W1, g_bh1);            // 2
    k_split_w<128><<<(NR * HID * 128 + 255) / 256, 256>>>(W2, g_bh2);          // 3
    k_wmma<64><<<ggrid, 256, SMEM>>>(g_bh1, as1, ad1);                         // 4 <- ncu

    // CSR build (independent of GEMM results)
    k_zero_counters<<<(NR * NN + 255) / 256, 256>>>();
    k_hist<<<(NR * NE + 255) / 256, 256>>>(ei);
    k_scanA<<<dim3(NBLK, NR), 1024>>>();
    k_scanB<<<1, 32>>>();
    k_scanC<<<dim3(NBLK, NR), 1024>>>();
    k_scatter<<<(NR * NE + 255) / 256, 256>>>(ei);

    // ---- layer 1: agg (warp per relation) + softsign + LN fused ----
    k_agg_ln<true><<<NN, 192>>>(b1, g1, be1);

    // ---- layer 2 ----
    k_wmma<128><<<ggrid, 256, SMEM>>>(g_bh2, as2, ad2);
    k_agg_ln<false><<<NN, 192>>>(b2, g2, be2);

    // ---- attention pooling + projection ----
    k_scores<<<warpgrid, 256>>>(q);
    k_gstart<<<(NN + 255) / 256, 256>>>(batch);
    k_pool<<<NG, 128>>>();
    k_proj<<<NG, 128>>>(Wp, bp, out);
}

// round 15
// speedup vs baseline: 1.2522x; 1.2522x over previous
#include <cuda_runtime.h>
#include <cuda_fp16.h>
#include <cstdint>
#include <cstddef>

#define NN   100000
#define NE   500000
#define NR   6
#define HID  128
#define NG   1024
#define NBLK 98          // ceil(NN / 1024)
#define TM   128
#define GEMM_GRID ((NN + TM - 1) / TM)   // 782

// ---------------- scratch (static device globals; no allocation) ----------------
__device__ __align__(16) __half g_h6[(size_t)NR * NN * HID];  // per-relation h (fp16)
__device__ __align__(16) float g_act[(size_t)NN * HID];
__device__ __align__(16) float g_als6[(size_t)NR * NN * 4];
__device__ __align__(16) float g_ald6[(size_t)NR * NN * 4];
__device__ __align__(16) __half g_ah[(size_t)NN * HID];       // fp16 activations
__device__ __align__(16) __half g_bh1[NR * HID * 64];         // layer1 W fp16 [r][n][k]
__device__ __align__(16) __half g_bh2[NR * HID * HID];        // layer2 W fp16 [r][n][k]
__device__ int   g_deg[NR * NN];
__device__ int   g_cursor[NR * NN];
__device__ int   g_rowptr[NR * (NN + 1)];
__device__ int   g_csrc[(size_t)NR * NE];
__device__ int   g_bsum[NR * 128];
__device__ int   g_gstart[NG + 1];
__device__ float g_scores[NN];
__device__ __align__(16) float g_pooled[NG * HID];

__device__ __forceinline__ uint32_t smem_to_u32(const void* p) {
    uint32_t a;
    asm("{ .reg .u64 t; cvta.to.shared.u64 t, %1; cvt.u32.u64 %0, t; }" : "=r"(a) : "l"(p));
    return a;
}

#define LDSM4(d, addr) \
    asm volatile("ldmatrix.sync.aligned.m8n8.x4.shared.b16 {%0,%1,%2,%3}, [%4];" \
        : "=r"((d)[0]), "=r"((d)[1]), "=r"((d)[2]), "=r"((d)[3]) : "r"(addr))

#define MMAF16(c, a, b0, b1) \
    asm volatile("mma.sync.aligned.m16n8k16.row.col.f32.f16.f16.f32 " \
        "{%0,%1,%2,%3}, {%4,%5,%6,%7}, {%8,%9}, {%0,%1,%2,%3};" \
        : "+f"((c)[0]), "+f"((c)[1]), "+f"((c)[2]), "+f"((c)[3]) \
        : "r"((a)[0]), "r"((a)[1]), "r"((a)[2]), "r"((a)[3]), "r"(b0), "r"(b1))

// ---------------- CSR build ----------------
__global__ void k_zero_counters() {
    int i = blockIdx.x * blockDim.x + threadIdx.x;
    if (i < NR * NN) { g_deg[i] = 0; g_cursor[i] = 0; }
}
__global__ void k_hist(const int* __restrict__ ei) {
    int i = blockIdx.x * blockDim.x + threadIdx.x;
    if (i >= NR * NE) return;
    int r = i / NE, e = i - r * NE;
    int dst = ei[((size_t)r * 2 + 1) * NE + e];
    atomicAdd(&g_deg[r * NN + dst], 1);
}
__global__ void k_scanA() {
    __shared__ int sh[1024];
    int r = blockIdx.y, blk = blockIdx.x, t = threadIdx.x;
    int n = blk * 1024 + t;
    int v = (n < NN) ? g_deg[r * NN + n] : 0;
    sh[t] = v;
    __syncthreads();
    for (int off = 1; off < 1024; off <<= 1) {
        int add = (t >= off) ? sh[t - off] : 0;
        __syncthreads();
        sh[t] += add;
        __syncthreads();
    }
    if (n < NN) g_rowptr[r * (NN + 1) + n + 1] = sh[t];
    if (t == 1023) g_bsum[r * 128 + blk] = sh[t];
}
__global__ void k_scanB() {
    int r = threadIdx.x;
    if (r >= NR) return;
    int run = 0;
    for (int b = 0; b < NBLK; b++) {
        int v = g_bsum[r * 128 + b];
        g_bsum[r * 128 + b] = run;
        run += v;
    }
}
__global__ void k_scanC() {
    int r = blockIdx.y, blk = blockIdx.x, t = threadIdx.x;
    int n = blk * 1024 + t;
    if (n < NN) g_rowptr[r * (NN + 1) + n + 1] += g_bsum[r * 128 + blk];
    if (n == 0) g_rowptr[r * (NN + 1)] = 0;
}
__global__ void k_scatter(const int* __restrict__ ei) {
    int i = blockIdx.x * blockDim.x + threadIdx.x;
    if (i >= NR * NE) return;
    int r = i / NE, e = i - r * NE;
    int src = ei[((size_t)r * 2 + 0) * NE + e];
    int dst = ei[((size_t)r * 2 + 1) * NE + e];
    int pos = g_rowptr[r * (NN + 1) + dst] + atomicAdd(&g_cursor[r * NN + dst], 1);
    g_csrc[(size_t)r * NE + pos] = src;
}

// ---------------- fp16 convert precompute ----------------
template <int K>
__global__ void k_split_a(const float* __restrict__ A) {
    int i = blockIdx.x * blockDim.x + threadIdx.x;
    if (i >= NN * K) return;
    g_ah[i] = __float2half(A[i]);
}
template <int K>
__global__ void k_split_w(const float* __restrict__ W, __half* __restrict__ Bh) {
    int i = blockIdx.x * blockDim.x + threadIdx.x;   // over NR*HID*K, [r][n][k]
    if (i >= NR * HID * K) return;
    int k = i % K;
    int n = (i / K) % HID;
    int r = i / (K * HID);
    Bh[i] = __float2half(W[((size_t)r * K + k) * HID + n]);
}

// ---------------- mma.sync fp16 GEMM + fused logits ----------------
// blockIdx.y = relation. K chunked by 64. D[128,128] = A@W^T, fp32 accum, fp16 out.
template <int K>
__global__ __launch_bounds__(256, 2)
void k_wmma(const __half* __restrict__ BhAll,
            const float* __restrict__ asrcAll, const float* __restrict__ adstAll) {
    constexpr int CH = 64;                 // K-chunk width
    constexpr int NCH = K / CH;
    constexpr int STRIDE = CH * 2 + 16;    // 144 bytes per row
    constexpr int TS = 128 * STRIDE;       // 18432 per tile
    constexpr int SEGS = CH / 8;           // 8 16B segments per row
    extern __shared__ char smem[];
    __shared__ float s_as[128], s_ad[128];
    const int tid = threadIdx.x;
    const int wid = tid >> 5, lane = tid & 31;
    const int warprow = wid & 3, warpcol = wid >> 2;
    const int row0 = blockIdx.x * TM;
    const int r = blockIdx.y;
    const __half* Bh = BhAll + (size_t)r * HID * K;

    if (tid < 128) { s_as[tid] = asrcAll[r * HID + tid]; s_ad[tid] = adstAll[r * HID + tid]; }

    const uint32_t sb = smem_to_u32(smem);
    const uint32_t aAddr = sb + (uint32_t)((warprow * 32 + (lane & 15)) * STRIDE + (((lane >> 4) << 3) << 1));
    const uint32_t bAddr = sb + TS +
        (uint32_t)((warpcol * 64 + (lane & 7) + ((lane >> 4) << 3)) * STRIDE + ((lane & 8) << 1));

    float acc[2][8][4];
#pragma unroll
    for (int mt = 0; mt < 2; mt++)
#pragma unroll
        for (int nt = 0; nt < 8; nt++)
#pragma unroll
            for (int j = 0; j < 4; j++) acc[mt][nt][j] = 0.0f;

    for (int c = 0; c < NCH; c++) {
        for (int u = tid; u < 128 * SEGS; u += 256) {
            int row = u >> 3, seg = u & 7;
            uint4 va = make_uint4(0, 0, 0, 0);
            if (row0 + row < NN) {
                size_t g = (size_t)(row0 + row) * K + c * CH + seg * 8;
                va = *(const uint4*)(g_ah + g);
            }
            *(uint4*)(smem + 0 * TS + row * STRIDE + seg * 16) = va;
            size_t b = (size_t)row * K + c * CH + seg * 8;
            *(uint4*)(smem + 1 * TS + row * STRIDE + seg * 16) = *(const uint4*)(Bh + b);
        }
        __syncthreads();

#pragma unroll
        for (int k0 = 0; k0 < CH; k0 += 16) {
            uint32_t ah[2][4], bh[4][4];
#pragma unroll
            for (int mt = 0; mt < 2; mt++)
                LDSM4(ah[mt], aAddr + mt * 16 * STRIDE + k0 * 2);
#pragma unroll
            for (int j = 0; j < 4; j++)
                LDSM4(bh[j], bAddr + j * 16 * STRIDE + k0 * 2);
#pragma unroll
            for (int mt = 0; mt < 2; mt++)
#pragma unroll
                for (int nt = 0; nt < 8; nt++) {
                    int j = nt >> 1, s = (nt & 1) * 2;
                    MMAF16(acc[mt][nt], ah[mt], bh[j][s], bh[j][s + 1]);
                }
        }
        __syncthreads();
    }

    // epilogue: store h (fp16) + fused attention logits
    const int quad = lane >> 2, ql = lane & 3;
    __half* Hout = g_h6 + (size_t)r * NN * HID;
    float ps[8], pd[8];
#pragma unroll
    for (int i = 0; i < 8; i++) { ps[i] = 0.f; pd[i] = 0.f; }

#pragma unroll
    for (int mt = 0; mt < 2; mt++) {
#pragma unroll
        for (int nt = 0; nt < 8; nt++) {
            int nc = warpcol * 64 + nt * 8 + 2 * ql;
            int hl = nt >> 2;
            float c0 = acc[mt][nt][0], c1 = acc[mt][nt][1];
            float c2 = acc[mt][nt][2], c3 = acc[mt][nt][3];
            ps[mt * 4 + 0 + hl] += c0 * s_as[nc] + c1 * s_as[nc + 1];
            pd[mt * 4 + 0 + hl] += c0 * s_ad[nc] + c1 * s_ad[nc + 1];
            ps[mt * 4 + 2 + hl] += c2 * s_as[nc] + c3 * s_as[nc + 1];
            pd[mt * 4 + 2 + hl] += c2 * s_ad[nc] + c3 * s_ad[nc + 1];
            int r0g = row0 + warprow * 32 + mt * 16 + quad;
            if (r0g < NN)
                *(__half2*)(Hout + (size_t)r0g * HID + nc) =
                    __floats2half2_rn(c0, c1);
            if (r0g + 8 < NN)
                *(__half2*)(Hout + (size_t)(r0g + 8) * HID + nc) =
                    __floats2half2_rn(c2, c3);
        }
    }
#pragma unroll
    for (int i = 0; i < 8; i++) {
        ps[i] += __shfl_xor_sync(0xffffffffu, ps[i], 1);
        ps[i] += __shfl_xor_sync(0xffffffffu, ps[i], 2);
        pd[i] += __shfl_xor_sync(0xffffffffu, pd[i], 1);
        pd[i] += __shfl_xor_sync(0xffffffffu, pd[i], 2);
    }
    if (ql == 0) {
#pragma unroll
        for (int mt = 0; mt < 2; mt++)
#pragma unroll
            for (int sub = 0; sub < 2; sub++) {
                int rg = row0 + warprow * 32 + mt * 16 + sub * 8 + quad;
                if (rg < NN) {
                    size_t off = ((size_t)rg) * 4 + warpcol * 2 + (size_t)r * NN * 4;
                    *(float2*)(g_als6 + off) =
                        make_float2(ps[mt * 4 + sub * 2 + 0], ps[mt * 4 + sub * 2 + 1]);
                    *(float2*)(g_ald6 + off) =
                        make_float2(pd[mt * 4 + sub * 2 + 0], pd[mt * 4 + sub * 2 + 1]);
                }
            }
    }
}

// ---------------- GAT aggregation + softsign + LN fused (warp per dst node) --------
// Lane owns channels [4*lane, 4*lane+4); head = lane>>3 -> ONE exp per lane per edge,
// ONE 8B vector h gather per lane per edge. Single-pass softmax (logits tiny).
// Layer 2 additionally fuses the pooling score dot-product.
template <bool EMIT_F16>
__global__ void k_agg_ln(const float* __restrict__ bias,
                         const float* __restrict__ gam, const float* __restrict__ bet,
                         const float* __restrict__ q) {
    int gw = (blockIdx.x * blockDim.x + threadIdx.x) >> 5;
    int lane = threadIdx.x & 31;
    if (gw >= NN) return;
    const int head = lane >> 3;
    float4 o = make_float4(0.f, 0.f, 0.f, 0.f);
#pragma unroll
    for (int r = 0; r < NR; r++) {
        float4 b4 = *(const float4*)(bias + r * HID + lane * 4);
        o.x += b4.x; o.y += b4.y; o.z += b4.z; o.w += b4.w;
    }
    for (int r = 0; r < NR; r++) {
        const int* rp = g_rowptr + r * (NN + 1);
        int e0 = rp[gw], e1 = rp[gw + 1];
        if (e0 == e1) continue;
        const int* csrc = g_csrc + (size_t)r * NE;
        const float* als = g_als6 + (size_t)r * NN * 4;
        const __half* H = g_h6 + (size_t)r * NN * HID;
        const float adH = g_ald6[((size_t)r * NN + gw) * 4 + head];

        float d = 0.f;
        float4 a = make_float4(0.f, 0.f, 0.f, 0.f);
        for (int e = e0; e < e1; e++) {
            int s = csrc[e];
            float t = als[(size_t)s * 4 + head] + adH;
            t = t > 0.f ? t : 0.2f * t;
            float ex = __expf(t);
            d += ex;
            uint2 hraw = *(const uint2*)(H + (size_t)s * HID + lane * 4);
            float2 f01 = __half22float2(*(__half2*)&hraw.x);
            float2 f23 = __half22float2(*(__half2*)&hraw.y);
            a.x += ex * f01.x; a.y += ex * f01.y;
            a.z += ex * f23.x; a.w += ex * f23.y;
        }
        float inv = 1.0f / (d + 1e-16f);
        o.x += a.x * inv; o.y += a.y * inv;
        o.z += a.z * inv; o.w += a.w * inv;
    }

    // softsign
    float s0 = o.x / (1.0f + fabsf(o.x));
    float s1 = o.y / (1.0f + fabsf(o.y));
    float s2 = o.z / (1.0f + fabsf(o.z));
    float s3 = o.w / (1.0f + fabsf(o.w));
    // LayerNorm across warp (128 channels)
    float sum = s0 + s1 + s2 + s3;
    float sq  = s0 * s0 + s1 * s1 + s2 * s2 + s3 * s3;
#pragma unroll
    for (int off = 16; off; off >>= 1) {
        sum += __shfl_xor_sync(0xffffffffu, sum, off);
        sq  += __shfl_xor_sync(0xffffffffu, sq, off);
    }
    float mu = sum * (1.0f / HID);
    float var = sq * (1.0f / HID) - mu * mu;
    float rs = rsqrtf(var + 1e-5f);
    float4 gm = *(const float4*)(gam + lane * 4);
    float4 bt = *(const float4*)(bet + lane * 4);
    float r0 = (s0 - mu) * rs * gm.x + bt.x;
    float r1 = (s1 - mu) * rs * gm.y + bt.y;
    float r2 = (s2 - mu) * rs * gm.z + bt.z;
    float r3 = (s3 - mu) * rs * gm.w + bt.w;
    if (EMIT_F16) {
        __half2 h01 = __floats2half2_rn(r0, r1);
        __half2 h23 = __floats2half2_rn(r2, r3);
        uint2 pk;
        pk.x = *(uint32_t*)&h01;
        pk.y = *(uint32_t*)&h23;
        *(uint2*)(g_ah + (size_t)gw * HID + lane * 4) = pk;
    } else {
        *(float4*)(g_act + (size_t)gw * HID + lane * 4) = make_float4(r0, r1, r2, r3);
        // fused pooling score: dot(row, q)
        float4 qq = *(const float4*)(q + lane * 4);
        float sc = r0 * qq.x + r1 * qq.y + r2 * qq.z + r3 * qq.w;
#pragma unroll
        for (int off = 16; off; off >>= 1) sc += __shfl_xor_sync(0xffffffffu, sc, off);
        if (lane == 0) g_scores[gw] = sc;
    }
}

// ---------------- pooling ----------------
__global__ void k_gstart(const int* __restrict__ batch) {
    int n = blockIdx.x * blockDim.x + threadIdx.x;
    if (n >= NN) return;
    int b = batch[n];
    if (n == 0) {
        for (int g = 0; g <= b; g++) g_gstart[g] = 0;
    } else {
        int pb = batch[n - 1];
        for (int g = pb + 1; g <= b; g++) g_gstart[g] = n;
    }
    if (n == NN - 1) {
        for (int g = b + 1; g <= NG; g++) g_gstart[g] = NN;
    }
}

__global__ __launch_bounds__(128) void k_pool() {
    int g = blockIdx.x, t = threadIdx.x;
    int s = g_gstart[g], e = g_gstart[g + 1];
    __shared__ float red[128];
    __shared__ float sex[128];
    float m = -3.4e38f;
    for (int n = s + t; n < e; n += 128) m = fmaxf(m, g_scores[n]);
    red[t] = m;
    __syncthreads();
    for (int off = 64; off; off >>= 1) {
        if (t < off) red[t] = fmaxf(red[t], red[t + off]);
        __syncthreads();
    }
    m = red[0];
    __syncthreads();
    float acc = 0.f, den = 0.f;
    for (int base = s; base < e; base += 128) {
        int idx = base + t;
        float ex = (idx < e) ? __expf(g_scores[idx] - m) : 0.0f;
        den += ex;
        sex[t] = ex;
        __syncthreads();
        int lim = e - base; if (lim > 128) lim = 128;
        for (int j = 0; j < lim; j++)
            acc += sex[j] * g_act[(size_t)(base + j) * HID + t];
        __syncthreads();
    }
    red[t] = den;
    __syncthreads();
    for (int off = 64; off; off >>= 1) {
        if (t < off) red[t] += red[t + off];
        __syncthreads();
    }
    g_pooled[g * HID + t] = acc / (red[0] + 1e-16f);
}

__global__ __launch_bounds__(128) void k_proj(const float* __restrict__ Wp,
                                              const float* __restrict__ bp,
                                              float* __restrict__ out) {
    int g = blockIdx.x, t = threadIdx.x;
    float acc = bp[t];
    const float* p = g_pooled + g * HID;
#pragma unroll 8
    for (int k = 0; k < HID; k++) acc += p[k] * Wp[k * HID + t];
    out[g * HID + t] = acc;
}

// ---------------- orchestration ----------------
extern "C" void kernel_launch(void* const* d_in, const int* in_sizes, int n_in,
                              void* d_out, int out_size) {
    const float* x    = (const float*)d_in[0];
    const int*   ei   = (const int*)d_in[1];
    const int*   batch= (const int*)d_in[2];
    const float* W1  = (const float*)d_in[3];
    const float* as1 = (const float*)d_in[4];
    const float* ad1 = (const float*)d_in[5];
    const float* b1  = (const float*)d_in[6];
    const float* W2  = (const float*)d_in[7];
    const float* as2 = (const float*)d_in[8];
    const float* ad2 = (const float*)d_in[9];
    const float* b2  = (const float*)d_in[10];
    const float* g1  = (const float*)d_in[11];
    const float* be1 = (const float*)d_in[12];
    const float* g2  = (const float*)d_in[13];
    const float* be2 = (const float*)d_in[14];
    const float* q   = (const float*)d_in[15];
    const float* Wp  = (const float*)d_in[16];
    const float* bp  = (const float*)d_in[17];
    float* out = (float*)d_out;

    const int SMEM = 2 * 128 * (64 * 2 + 16);    // 36864 (A tile + B tile)
    cudaFuncSetAttribute(k_wmma<64>,  cudaFuncAttributeMaxDynamicSharedMemorySize, SMEM);
    cudaFuncSetAttribute(k_wmma<128>, cudaFuncAttributeMaxDynamicSharedMemorySize, SMEM);

    const int warpgrid = (NN * 32 + 255) / 256;
    const dim3 ggrid(GEMM_GRID, NR);

    // ncu profiles launch #4 -> layer-1 GEMM there
    k_split_a<64><<<(NN * 64 + 255) / 256, 256>>>(x);                          // 1
    k_split_w<64><<<(NR * HID * 64 + 255) / 256, 256>>>(W1, g_bh1);            // 2
    k_split_w<128><<<(NR * HID * 128 + 255) / 256, 256>>>(W2, g_bh2);          // 3
    k_wmma<64><<<ggrid, 256, SMEM>>>(g_bh1, as1, ad1);                         // 4 <- ncu

    // CSR build (independent of GEMM results)
    k_zero_counters<<<(NR * NN + 255) / 256, 256>>>();
    k_hist<<<(NR * NE + 255) / 256, 256>>>(ei);
    k_scanA<<<dim3(NBLK, NR), 1024>>>();
    k_scanB<<<1, 32>>>();
    k_scanC<<<dim3(NBLK, NR), 1024>>>();
    k_scatter<<<(NR * NE + 255) / 256, 256>>>(ei);

    // ---- layer 1: agg + softsign + LN fused, emits fp16 activations ----
    k_agg_ln<true><<<warpgrid, 256>>>(b1, g1, be1, nullptr);

    // ---- layer 2 (scores fused into agg epilogue) ----
    k_wmma<128><<<ggrid, 256, SMEM>>>(g_bh2, as2, ad2);
    k_agg_ln<false><<<warpgrid, 256>>>(b2, g2, be2, q);

    // ---- attention pooling + projection ----
    k_gstart<<<(NN + 255) / 256, 256>>>(batch);
    k_pool<<<NG, 128>>>();
    k_proj<<<NG, 128>>>(Wp, bp, out);
}

// round 16
// speedup vs baseline: 1.3265x; 1.0594x over previous
#include <cuda_runtime.h>
#include <cuda_fp16.h>
#include <cstdint>
#include <cstddef>

#define NN   100000
#define NE   500000
#define NR   6
#define HID  128
#define NG   1024
#define NBLK 98          // ceil(NN / 1024)
#define TM   128
#define GEMM_GRID ((NN + TM - 1) / TM)   // 782

// ---------------- scratch (static device globals; no allocation) ----------------
__device__ __align__(16) __half g_h6[(size_t)NR * NN * HID];  // per-relation h (fp16)
__device__ __align__(16) float g_act[(size_t)NN * HID];
__device__ __align__(16) float g_als6[(size_t)NR * NN * 4];
__device__ __align__(16) float g_ald6[(size_t)NR * NN * 4];
__device__ __align__(16) __half g_ah[(size_t)NN * HID];       // fp16 activations (layer2 input)
__device__ __align__(16) __half g_bh1[NR * HID * 64];         // layer1 W fp16 [r][n][k]
__device__ __align__(16) __half g_bh2[NR * HID * HID];        // layer2 W fp16 [r][n][k]
__device__ int   g_deg[NR * NN];
__device__ int   g_cursor[NR * NN];
__device__ int   g_rowptr[NR * (NN + 1)];
__device__ int   g_csrc[(size_t)NR * NE];
__device__ int   g_bsum[NR * 128];
__device__ int   g_gstart[NG + 1];
__device__ float g_scores[NN];
__device__ __align__(16) float g_pooled[NG * HID];

__device__ __forceinline__ uint32_t smem_to_u32(const void* p) {
    uint32_t a;
    asm("{ .reg .u64 t; cvta.to.shared.u64 t, %1; cvt.u32.u64 %0, t; }" : "=r"(a) : "l"(p));
    return a;
}

#define LDSM4(d, addr) \
    asm volatile("ldmatrix.sync.aligned.m8n8.x4.shared.b16 {%0,%1,%2,%3}, [%4];" \
        : "=r"((d)[0]), "=r"((d)[1]), "=r"((d)[2]), "=r"((d)[3]) : "r"(addr))

#define MMAF16(c, a, b0, b1) \
    asm volatile("mma.sync.aligned.m16n8k16.row.col.f32.f16.f16.f32 " \
        "{%0,%1,%2,%3}, {%4,%5,%6,%7}, {%8,%9}, {%0,%1,%2,%3};" \
        : "+f"((c)[0]), "+f"((c)[1]), "+f"((c)[2]), "+f"((c)[3]) \
        : "r"((a)[0]), "r"((a)[1]), "r"((a)[2]), "r"((a)[3]), "r"(b0), "r"(b1))

// ---------------- CSR build ----------------
__global__ void k_zero_counters() {
    int i = blockIdx.x * blockDim.x + threadIdx.x;
    if (i < NR * NN) { g_deg[i] = 0; g_cursor[i] = 0; }
}
__global__ void k_hist(const int* __restrict__ ei) {
    int i = blockIdx.x * blockDim.x + threadIdx.x;
    if (i >= NR * NE) return;
    int r = i / NE, e = i - r * NE;
    int dst = ei[((size_t)r * 2 + 1) * NE + e];
    atomicAdd(&g_deg[r * NN + dst], 1);
}
__global__ void k_scanA() {
    __shared__ int sh[1024];
    int r = blockIdx.y, blk = blockIdx.x, t = threadIdx.x;
    int n = blk * 1024 + t;
    int v = (n < NN) ? g_deg[r * NN + n] : 0;
    sh[t] = v;
    __syncthreads();
    for (int off = 1; off < 1024; off <<= 1) {
        int add = (t >= off) ? sh[t - off] : 0;
        __syncthreads();
        sh[t] += add;
        __syncthreads();
    }
    if (n < NN) g_rowptr[r * (NN + 1) + n + 1] = sh[t];
    if (t == 1023) g_bsum[r * 128 + blk] = sh[t];
}
__global__ void k_scanB() {
    int r = threadIdx.x;
    if (r >= NR) return;
    int run = 0;
    for (int b = 0; b < NBLK; b++) {
        int v = g_bsum[r * 128 + b];
        g_bsum[r * 128 + b] = run;
        run += v;
    }
}
__global__ void k_scanC() {
    int r = blockIdx.y, blk = blockIdx.x, t = threadIdx.x;
    int n = blk * 1024 + t;
    if (n < NN) g_rowptr[r * (NN + 1) + n + 1] += g_bsum[r * 128 + blk];
    if (n == 0) g_rowptr[r * (NN + 1)] = 0;
}
__global__ void k_scatter(const int* __restrict__ ei) {
    int i = blockIdx.x * blockDim.x + threadIdx.x;
    if (i >= NR * NE) return;
    int r = i / NE, e = i - r * NE;
    int src = ei[((size_t)r * 2 + 0) * NE + e];
    int dst = ei[((size_t)r * 2 + 1) * NE + e];
    int pos = g_rowptr[r * (NN + 1) + dst] + atomicAdd(&g_cursor[r * NN + dst], 1);
    g_csrc[(size_t)r * NE + pos] = src;
}

// ---------------- fp16 weight precompute ----------------
template <int K>
__global__ void k_split_w(const float* __restrict__ W, __half* __restrict__ Bh) {
    int i = blockIdx.x * blockDim.x + threadIdx.x;   // over NR*HID*K, [r][n][k]
    if (i >= NR * HID * K) return;
    int k = i % K;
    int n = (i / K) % HID;
    int r = i / (K * HID);
    Bh[i] = __float2half(W[((size_t)r * K + k) * HID + n]);
}

// ---------------- mma.sync fp16 GEMM + fused logits ----------------
// blockIdx.y = relation. K chunked by 64. D[128,128] = A@W^T, fp32 accum, fp16 out.
// AF32: A loaded from fp32 source (layer1 x) and converted in the tile fill;
// otherwise A comes from g_ah (fp16).
template <int K, bool AF32>
__global__ __launch_bounds__(256, 2)
void k_wmma(const float* __restrict__ Axf, const __half* __restrict__ BhAll,
            const float* __restrict__ asrcAll, const float* __restrict__ adstAll) {
    constexpr int CH = 64;                 // K-chunk width
    constexpr int NCH = K / CH;
    constexpr int STRIDE = CH * 2 + 16;    // 144 bytes per row
    constexpr int TS = 128 * STRIDE;       // 18432 per tile
    constexpr int SEGS = CH / 8;           // 8 16B segments per row
    extern __shared__ char smem[];
    __shared__ float s_as[128], s_ad[128];
    const int tid = threadIdx.x;
    const int wid = tid >> 5, lane = tid & 31;
    const int warprow = wid & 3, warpcol = wid >> 2;
    const int row0 = blockIdx.x * TM;
    const int r = blockIdx.y;
    const __half* Bh = BhAll + (size_t)r * HID * K;

    if (tid < 128) { s_as[tid] = asrcAll[r * HID + tid]; s_ad[tid] = adstAll[r * HID + tid]; }

    const uint32_t sb = smem_to_u32(smem);
    const uint32_t aAddr = sb + (uint32_t)((warprow * 32 + (lane & 15)) * STRIDE + (((lane >> 4) << 3) << 1));
    const uint32_t bAddr = sb + TS +
        (uint32_t)((warpcol * 64 + (lane & 7) + ((lane >> 4) << 3)) * STRIDE + ((lane & 8) << 1));

    float acc[2][8][4];
#pragma unroll
    for (int mt = 0; mt < 2; mt++)
#pragma unroll
        for (int nt = 0; nt < 8; nt++)
#pragma unroll
            for (int j = 0; j < 4; j++) acc[mt][nt][j] = 0.0f;

    for (int c = 0; c < NCH; c++) {
        for (int u = tid; u < 128 * SEGS; u += 256) {
            int row = u >> 3, seg = u & 7;
            uint4 va = make_uint4(0, 0, 0, 0);
            if (row0 + row < NN) {
                size_t g = (size_t)(row0 + row) * K + c * CH + seg * 8;
                if (AF32) {
                    const float4* xr = (const float4*)(Axf + g);
                    float4 f0 = xr[0], f1 = xr[1];
                    __half2 p0 = __floats2half2_rn(f0.x, f0.y);
                    __half2 p1 = __floats2half2_rn(f0.z, f0.w);
                    __half2 p2 = __floats2half2_rn(f1.x, f1.y);
                    __half2 p3 = __floats2half2_rn(f1.z, f1.w);
                    va.x = *(uint32_t*)&p0; va.y = *(uint32_t*)&p1;
                    va.z = *(uint32_t*)&p2; va.w = *(uint32_t*)&p3;
                } else {
                    va = *(const uint4*)(g_ah + g);
                }
            }
            *(uint4*)(smem + 0 * TS + row * STRIDE + seg * 16) = va;
            size_t b = (size_t)row * K + c * CH + seg * 8;
            *(uint4*)(smem + 1 * TS + row * STRIDE + seg * 16) = *(const uint4*)(Bh + b);
        }
        __syncthreads();

#pragma unroll
        for (int k0 = 0; k0 < CH; k0 += 16) {
            uint32_t ah[2][4], bh[4][4];
#pragma unroll
            for (int mt = 0; mt < 2; mt++)
                LDSM4(ah[mt], aAddr + mt * 16 * STRIDE + k0 * 2);
#pragma unroll
            for (int j = 0; j < 4; j++)
                LDSM4(bh[j], bAddr + j * 16 * STRIDE + k0 * 2);
#pragma unroll
            for (int mt = 0; mt < 2; mt++)
#pragma unroll
                for (int nt = 0; nt < 8; nt++) {
                    int j = nt >> 1, s = (nt & 1) * 2;
                    MMAF16(acc[mt][nt], ah[mt], bh[j][s], bh[j][s + 1]);
                }
        }
        __syncthreads();
    }

    // epilogue: store h (fp16) + fused attention logits
    const int quad = lane >> 2, ql = lane & 3;
    __half* Hout = g_h6 + (size_t)r * NN * HID;
    float ps[8], pd[8];
#pragma unroll
    for (int i = 0; i < 8; i++) { ps[i] = 0.f; pd[i] = 0.f; }

#pragma unroll
    for (int mt = 0; mt < 2; mt++) {
#pragma unroll
        for (int nt = 0; nt < 8; nt++) {
            int nc = warpcol * 64 + nt * 8 + 2 * ql;
            int hl = nt >> 2;
            float c0 = acc[mt][nt][0], c1 = acc[mt][nt][1];
            float c2 = acc[mt][nt][2], c3 = acc[mt][nt][3];
            ps[mt * 4 + 0 + hl] += c0 * s_as[nc] + c1 * s_as[nc + 1];
            pd[mt * 4 + 0 + hl] += c0 * s_ad[nc] + c1 * s_ad[nc + 1];
            ps[mt * 4 + 2 + hl] += c2 * s_as[nc] + c3 * s_as[nc + 1];
            pd[mt * 4 + 2 + hl] += c2 * s_ad[nc] + c3 * s_ad[nc + 1];
            int r0g = row0 + warprow * 32 + mt * 16 + quad;
            if (r0g < NN)
                *(__half2*)(Hout + (size_t)r0g * HID + nc) =
                    __floats2half2_rn(c0, c1);
            if (r0g + 8 < NN)
                *(__half2*)(Hout + (size_t)(r0g + 8) * HID + nc) =
                    __floats2half2_rn(c2, c3);
        }
    }
#pragma unroll
    for (int i = 0; i < 8; i++) {
        ps[i] += __shfl_xor_sync(0xffffffffu, ps[i], 1);
        ps[i] += __shfl_xor_sync(0xffffffffu, ps[i], 2);
        pd[i] += __shfl_xor_sync(0xffffffffu, pd[i], 1);
        pd[i] += __shfl_xor_sync(0xffffffffu, pd[i], 2);
    }
    if (ql == 0) {
#pragma unroll
        for (int mt = 0; mt < 2; mt++)
#pragma unroll
            for (int sub = 0; sub < 2; sub++) {
                int rg = row0 + warprow * 32 + mt * 16 + sub * 8 + quad;
                if (rg < NN) {
                    size_t off = ((size_t)rg) * 4 + warpcol * 2 + (size_t)r * NN * 4;
                    *(float2*)(g_als6 + off) =
                        make_float2(ps[mt * 4 + sub * 2 + 0], ps[mt * 4 + sub * 2 + 1]);
                    *(float2*)(g_ald6 + off) =
                        make_float2(pd[mt * 4 + sub * 2 + 0], pd[mt * 4 + sub * 2 + 1]);
                }
            }
    }
}

// ---------------- GAT aggregation + softsign + LN fused (warp per dst node) --------
// Lane owns channels [4*lane, 4*lane+4); head = lane>>3. Single-pass softmax.
// Edge loop software-pipelined: csrc prefetched 2 ahead, als/h 1 ahead.
// Layer 2 additionally fuses the pooling score dot-product.
template <bool EMIT_F16>
__global__ void k_agg_ln(const float* __restrict__ bias,
                         const float* __restrict__ gam, const float* __restrict__ bet,
                         const float* __restrict__ q) {
    int gw = (blockIdx.x * blockDim.x + threadIdx.x) >> 5;
    int lane = threadIdx.x & 31;
    if (gw >= NN) return;
    const int head = lane >> 3;
    float4 o = make_float4(0.f, 0.f, 0.f, 0.f);
#pragma unroll
    for (int r = 0; r < NR; r++) {
        float4 b4 = *(const float4*)(bias + r * HID + lane * 4);
        o.x += b4.x; o.y += b4.y; o.z += b4.z; o.w += b4.w;
    }
    for (int r = 0; r < NR; r++) {
        const int* rp = g_rowptr + r * (NN + 1);
        int e0 = rp[gw], e1 = rp[gw + 1];
        if (e0 == e1) continue;
        const int* csrc = g_csrc + (size_t)r * NE;
        const float* als = g_als6 + (size_t)r * NN * 4;
        const __half* H = g_h6 + (size_t)r * NN * HID;
        const float adH = g_ald6[((size_t)r * NN + gw) * 4 + head];

        float d = 0.f;
        float4 a = make_float4(0.f, 0.f, 0.f, 0.f);

        // pipelined edge loop
        int s_cur = __ldg(csrc + e0);
        int s_nxt = (e0 + 1 < e1) ? __ldg(csrc + e0 + 1) : 0;
        float t_cur = __ldg(als + (size_t)s_cur * 4 + head);
        uint2 h_cur = __ldg((const uint2*)(H + (size_t)s_cur * HID + lane * 4));
        for (int e = e0; e < e1; e++) {
            int s_nn = (e + 2 < e1) ? __ldg(csrc + e + 2) : 0;
            float t_nxt = 0.f;
            uint2 h_nxt = make_uint2(0u, 0u);
            if (e + 1 < e1) {
                t_nxt = __ldg(als + (size_t)s_nxt * 4 + head);
                h_nxt = __ldg((const uint2*)(H + (size_t)s_nxt * HID + lane * 4));
            }
            float t = t_cur + adH;
            t = t > 0.f ? t : 0.2f * t;
            float ex = __expf(t);
            d += ex;
            float2 f01 = __half22float2(*(__half2*)&h_cur.x);
            float2 f23 = __half22float2(*(__half2*)&h_cur.y);
            a.x += ex * f01.x; a.y += ex * f01.y;
            a.z += ex * f23.x; a.w += ex * f23.y;
            s_cur = s_nxt; s_nxt = s_nn;
            t_cur = t_nxt; h_cur = h_nxt;
        }
        float inv = 1.0f / (d + 1e-16f);
        o.x += a.x * inv; o.y += a.y * inv;
        o.z += a.z * inv; o.w += a.w * inv;
    }

    // softsign
    float s0 = o.x / (1.0f + fabsf(o.x));
    float s1 = o.y / (1.0f + fabsf(o.y));
    float s2 = o.z / (1.0f + fabsf(o.z));
    float s3 = o.w / (1.0f + fabsf(o.w));
    // LayerNorm across warp (128 channels)
    float sum = s0 + s1 + s2 + s3;
    float sq  = s0 * s0 + s1 * s1 + s2 * s2 + s3 * s3;
#pragma unroll
    for (int off = 16; off; off >>= 1) {
        sum += __shfl_xor_sync(0xffffffffu, sum, off);
        sq  += __shfl_xor_sync(0xffffffffu, sq, off);
    }
    float mu = sum * (1.0f / HID);
    float var = sq * (1.0f / HID) - mu * mu;
    float rs = rsqrtf(var + 1e-5f);
    float4 gm = *(const float4*)(gam + lane * 4);
    float4 bt = *(const float4*)(bet + lane * 4);
    float r0 = (s0 - mu) * rs * gm.x + bt.x;
    float r1 = (s1 - mu) * rs * gm.y + bt.y;
    float r2 = (s2 - mu) * rs * gm.z + bt.z;
    float r3 = (s3 - mu) * rs * gm.w + bt.w;
    if (EMIT_F16) {
        __half2 h01 = __floats2half2_rn(r0, r1);
        __half2 h23 = __floats2half2_rn(r2, r3);
        uint2 pk;
        pk.x = *(uint32_t*)&h01;
        pk.y = *(uint32_t*)&h23;
        *(uint2*)(g_ah + (size_t)gw * HID + lane * 4) = pk;
    } else {
        *(float4*)(g_act + (size_t)gw * HID + lane * 4) = make_float4(r0, r1, r2, r3);
        // fused pooling score: dot(row, q)
        float4 qq = *(const float4*)(q + lane * 4);
        float sc = r0 * qq.x + r1 * qq.y + r2 * qq.z + r3 * qq.w;
#pragma unroll
        for (int off = 16; off; off >>= 1) sc += __shfl_xor_sync(0xffffffffu, sc, off);
        if (lane == 0) g_scores[gw] = sc;
    }
}

// ---------------- pooling ----------------
__global__ void k_gstart(const int* __restrict__ batch) {
    int n = blockIdx.x * blockDim.x + threadIdx.x;
    if (n >= NN) return;
    int b = batch[n];
    if (n == 0) {
        for (int g = 0; g <= b; g++) g_gstart[g] = 0;
    } else {
        int pb = batch[n - 1];
        for (int g = pb + 1; g <= b; g++) g_gstart[g] = n;
    }
    if (n == NN - 1) {
        for (int g = b + 1; g <= NG; g++) g_gstart[g] = NN;
    }
}

__global__ __launch_bounds__(128) void k_pool() {
    int g = blockIdx.x, t = threadIdx.x;
    int s = g_gstart[g], e = g_gstart[g + 1];
    __shared__ float red[128];
    __shared__ float sex[128];
    float m = -3.4e38f;
    for (int n = s + t; n < e; n += 128) m = fmaxf(m, g_scores[n]);
    red[t] = m;
    __syncthreads();
    for (int off = 64; off; off >>= 1) {
        if (t < off) red[t] = fmaxf(red[t], red[t + off]);
        __syncthreads();
    }
    m = red[0];
    __syncthreads();
    float acc = 0.f, den = 0.f;
    for (int base = s; base < e; base += 128) {
        int idx = base + t;
        float ex = (idx < e) ? __expf(g_scores[idx] - m) : 0.0f;
        den += ex;
        sex[t] = ex;
        __syncthreads();
        int lim = e - base; if (lim > 128) lim = 128;
        for (int j = 0; j < lim; j++)
            acc += sex[j] * g_act[(size_t)(base + j) * HID + t];
        __syncthreads();
    }
    red[t] = den;
    __syncthreads();
    for (int off = 64; off; off >>= 1) {
        if (t < off) red[t] += red[t + off];
        __syncthreads();
    }
    g_pooled[g * HID + t] = acc / (red[0] + 1e-16f);
}

__global__ __launch_bounds__(128) void k_proj(const float* __restrict__ Wp,
                                              const float* __restrict__ bp,
                                              float* __restrict__ out) {
    int g = blockIdx.x, t = threadIdx.x;
    float acc = bp[t];
    const float* p = g_pooled + g * HID;
#pragma unroll 8
    for (int k = 0; k < HID; k++) acc += p[k] * Wp[k * HID + t];
    out[g * HID + t] = acc;
}

// ---------------- orchestration ----------------
extern "C" void kernel_launch(void* const* d_in, const int* in_sizes, int n_in,
                              void* d_out, int out_size) {
    const float* x    = (const float*)d_in[0];
    const int*   ei   = (const int*)d_in[1];
    const int*   batch= (const int*)d_in[2];
    const float* W1  = (const float*)d_in[3];
    const float* as1 = (const float*)d_in[4];
    const float* ad1 = (const float*)d_in[5];
    const float* b1  = (const float*)d_in[6];
    const float* W2  = (const float*)d_in[7];
    const float* as2 = (const float*)d_in[8];
    const float* ad2 = (const float*)d_in[9];
    const float* b2  = (const float*)d_in[10];
    const float* g1  = (const float*)d_in[11];
    const float* be1 = (const float*)d_in[12];
    const float* g2  = (const float*)d_in[13];
    const float* be2 = (const float*)d_in[14];
    const float* q   = (const float*)d_in[15];
    const float* Wp  = (const float*)d_in[16];
    const float* bp  = (const float*)d_in[17];
    float* out = (float*)d_out;

    const int SMEM = 2 * 128 * (64 * 2 + 16);    // 36864 (A tile + B tile)
    cudaFuncSetAttribute(k_wmma<64, true>,   cudaFuncAttributeMaxDynamicSharedMemorySize, SMEM);
    cudaFuncSetAttribute(k_wmma<128, false>, cudaFuncAttributeMaxDynamicSharedMemorySize, SMEM);

    const int warpgrid = (NN * 32 + 255) / 256;
    const dim3 ggrid(GEMM_GRID, NR);

    // ncu profiles launch #4 -> layer-1 GEMM there
    k_split_w<64><<<(NR * HID * 64 + 255) / 256, 256>>>(W1, g_bh1);            // 1
    k_split_w<128><<<(NR * HID * 128 + 255) / 256, 256>>>(W2, g_bh2);          // 2
    k_zero_counters<<<(NR * NN + 255) / 256, 256>>>();                         // 3
    k_wmma<64, true><<<ggrid, 256, SMEM>>>(x, g_bh1, as1, ad1);                // 4 <- ncu

    // CSR build (independent of GEMM results)
    k_hist<<<(NR * NE + 255) / 256, 256>>>(ei);
    k_scanA<<<dim3(NBLK, NR), 1024>>>();
    k_scanB<<<1, 32>>>();
    k_scanC<<<dim3(NBLK, NR), 1024>>>();
    k_scatter<<<(NR * NE + 255) / 256, 256>>>(ei);

    // ---- layer 1: agg + softsign + LN fused, emits fp16 activations ----
    k_agg_ln<true><<<warpgrid, 256>>>(b1, g1, be1, nullptr);

    // ---- layer 2 (scores fused into agg epilogue) ----
    k_wmma<128, false><<<ggrid, 256, SMEM>>>(nullptr, g_bh2, as2, ad2);
    k_agg_ln<false><<<warpgrid, 256>>>(b2, g2, be2, q);

    // ---- attention pooling + projection ----
    k_gstart<<<(NN + 255) / 256, 256>>>(batch);
    k_pool<<<NG, 128>>>();
    k_proj<<<NG, 128>>>(Wp, bp, out);
}